// round 1
// baseline (speedup 1.0000x reference)
#include <cuda_runtime.h>
#include <math.h>

#define BB 8
#define CC 8
#define HH 256
#define WW 512
#define PLANE (HH*WW)
#define NPIX (BB*PLANE)
#define BANDH 8
#define NBANDS ((BB*HH)/BANDH)   /* 256 */
#define NITER 16
#define FULLMASK 0xffffffffu

// Scratch (allocation-free): gates, reciprocal weight-sums, depth ping-pong.
__device__ float g_buf[(size_t)BB*CC*PLANE];   // 32 MB
__device__ float r_buf[(size_t)BB*CC*PLANE];   // 32 MB
__device__ float d_bufA[NPIX];                 // 4 MB
__device__ float d_bufB[NPIX];                 // 4 MB

// ---------------------------------------------------------------------------
// Precompute: g = |guidance|, r = 1/(3x3 full sum of g), d0 = blend(blur,sparse)
// ---------------------------------------------------------------------------
__global__ __launch_bounds__(128, 2) void precompute_kernel(
    const float* __restrict__ guid,
    const float* __restrict__ blur,
    const float* __restrict__ sparse)
{
    const int lane = threadIdx.x & 31;
    const int warp = threadIdx.x >> 5;
    const int x0   = warp * 128 + lane * 4;
    const int band = blockIdx.x;
    const int b    = (band * BANDH) / HH;
    const int y0   = (band * BANDH) % HH;

    #pragma unroll 1
    for (int c = 0; c < CC; c++) {
        const float* gin  = guid  + ((size_t)(b * CC + c)) * PLANE;
        float*       gout = g_buf + ((size_t)(b * CC + c)) * PLANE;
        float*       rout = r_buf + ((size_t)(b * CC + c)) * PLANE;

        float4 rsp = make_float4(0.f, 0.f, 0.f, 0.f);
        float4 rsc = make_float4(0.f, 0.f, 0.f, 0.f);

        #pragma unroll
        for (int i = 0; i < BANDH + 2; i++) {
            const int  ry    = y0 - 1 + i;
            const bool valid = (ry >= 0) && (ry < HH);

            float4 ga = make_float4(0.f, 0.f, 0.f, 0.f);
            if (valid) {
                const float4 gv = *reinterpret_cast<const float4*>(gin + (size_t)ry * WW + x0);
                ga.x = fabsf(gv.x); ga.y = fabsf(gv.y);
                ga.z = fabsf(gv.z); ga.w = fabsf(gv.w);
            }
            float gm1 = __shfl_up_sync  (FULLMASK, ga.w, 1);
            float gp4 = __shfl_down_sync(FULLMASK, ga.x, 1);
            if (lane == 0)  gm1 = (valid && x0 > 0)      ? fabsf(gin[(size_t)ry * WW + x0 - 1]) : 0.f;
            if (lane == 31) gp4 = (valid && x0 + 4 < WW) ? fabsf(gin[(size_t)ry * WW + x0 + 4]) : 0.f;

            float4 rsn;
            {
                const float t01 = ga.x + ga.y, t12 = ga.y + ga.z, t23 = ga.z + ga.w;
                rsn.x = gm1 + t01; rsn.y = t01 + ga.z;
                rsn.z = t12 + ga.w; rsn.w = t23 + gp4;
            }

            if (valid && ry >= y0 && ry < y0 + BANDH) {
                *reinterpret_cast<float4*>(gout + (size_t)ry * WW + x0) = ga;
            }

            if (i >= 2) {
                const int yo = y0 + i - 2;
                float4 vs;
                vs.x = rsp.x + rsc.x + rsn.x;
                vs.y = rsp.y + rsc.y + rsn.y;
                vs.z = rsp.z + rsc.z + rsn.z;
                vs.w = rsp.w + rsc.w + rsn.w;
                float4 rv;
                rv.x = 1.0f / vs.x; rv.y = 1.0f / vs.y;
                rv.z = 1.0f / vs.z; rv.w = 1.0f / vs.w;
                *reinterpret_cast<float4*>(rout + (size_t)yo * WW + x0) = rv;
            }
            rsp = rsc; rsc = rsn;
        }
    }

    // d0 = sparse > 0 ? sparse : blur
    const float* sp = sparse + (size_t)b * PLANE;
    const float* bl = blur   + (size_t)b * PLANE;
    float*       dd = d_bufA + (size_t)b * PLANE;
    #pragma unroll
    for (int j = 0; j < BANDH; j++) {
        const int y = y0 + j;
        float4 s = *reinterpret_cast<const float4*>(sp + (size_t)y * WW + x0);
        float4 v = *reinterpret_cast<const float4*>(bl + (size_t)y * WW + x0);
        v.x = (s.x > 0.f) ? s.x : v.x;
        v.y = (s.y > 0.f) ? s.y : v.y;
        v.z = (s.z > 0.f) ? s.z : v.z;
        v.w = (s.w > 0.f) ? s.w : v.w;
        *reinterpret_cast<float4*>(dd + (size_t)y * WW + x0) = v;
    }
}

// ---------------------------------------------------------------------------
// One CSPN step:
//   d_new(p) = max_c [ r[c](p) * sum_{3x3} g[c](n)*d(n) ] , then sparse blend.
// Register column sweep; horizontal halo via shfl, vertical via rolling regs.
// ---------------------------------------------------------------------------
__global__ __launch_bounds__(128, 2) void iter_kernel(
    int src_sel,                    // 0: read d_bufA, 1: read d_bufB
    float* __restrict__ dst_ext,    // if non-null, write here (final iter)
    const float* __restrict__ sparse)
{
    const int lane = threadIdx.x & 31;
    const int warp = threadIdx.x >> 5;
    const int x0   = warp * 128 + lane * 4;
    const int band = blockIdx.x;
    const int b    = (band * BANDH) / HH;
    const int y0   = (band * BANDH) % HH;

    const float* dsrc = src_sel ? d_bufB : d_bufA;
    float*       ddst = dst_ext ? dst_ext : (src_sel ? d_bufA : d_bufB);
    const float* dsb  = dsrc + (size_t)b * PLANE;

    float4 m[BANDH];
    #pragma unroll
    for (int j = 0; j < BANDH; j++) m[j] = make_float4(0.f, 0.f, 0.f, 0.f);

    #pragma unroll 1
    for (int c = 0; c < CC; c++) {
        const float* gc = g_buf + ((size_t)(b * CC + c)) * PLANE;
        const float* rc = r_buf + ((size_t)(b * CC + c)) * PLANE;

        float4 rsp = make_float4(0.f, 0.f, 0.f, 0.f);
        float4 rsc = make_float4(0.f, 0.f, 0.f, 0.f);

        #pragma unroll
        for (int i = 0; i < BANDH + 2; i++) {
            const int  ry    = y0 - 1 + i;
            const bool valid = (ry >= 0) && (ry < HH);

            float4 gv = make_float4(0.f, 0.f, 0.f, 0.f);
            float4 dv = make_float4(0.f, 0.f, 0.f, 0.f);
            if (valid) {
                gv = *reinterpret_cast<const float4*>(gc  + (size_t)ry * WW + x0);
                dv = *reinterpret_cast<const float4*>(dsb + (size_t)ry * WW + x0);
            }
            float gm1 = __shfl_up_sync  (FULLMASK, gv.w, 1);
            float dm1 = __shfl_up_sync  (FULLMASK, dv.w, 1);
            float gp4 = __shfl_down_sync(FULLMASK, gv.x, 1);
            float dp4 = __shfl_down_sync(FULLMASK, dv.x, 1);
            if (lane == 0) {
                const bool e = valid && (x0 > 0);
                gm1 = e ? gc [(size_t)ry * WW + x0 - 1] : 0.f;
                dm1 = e ? dsb[(size_t)ry * WW + x0 - 1] : 0.f;
            }
            if (lane == 31) {
                const bool e = valid && (x0 + 4 < WW);
                gp4 = e ? gc [(size_t)ry * WW + x0 + 4] : 0.f;
                dp4 = e ? dsb[(size_t)ry * WW + x0 + 4] : 0.f;
            }

            const float um1 = gm1 * dm1;
            const float u0  = gv.x * dv.x;
            const float u1  = gv.y * dv.y;
            const float u2  = gv.z * dv.z;
            const float u3  = gv.w * dv.w;
            const float up4 = gp4 * dp4;

            float4 rsn;
            {
                const float t01 = u0 + u1, t12 = u1 + u2, t23 = u2 + u3;
                rsn.x = um1 + t01; rsn.y = t01 + u2;
                rsn.z = t12 + u3;  rsn.w = t23 + up4;
            }

            if (i >= 2) {
                const int yo = y0 + i - 2;
                const float4 rv = *reinterpret_cast<const float4*>(rc + (size_t)yo * WW + x0);
                float4 vs;
                vs.x = rsp.x + rsc.x + rsn.x;
                vs.y = rsp.y + rsc.y + rsn.y;
                vs.z = rsp.z + rsc.z + rsn.z;
                vs.w = rsp.w + rsc.w + rsn.w;
                const int j = i - 2;
                m[j].x = fmaxf(m[j].x, vs.x * rv.x);
                m[j].y = fmaxf(m[j].y, vs.y * rv.y);
                m[j].z = fmaxf(m[j].z, vs.z * rv.z);
                m[j].w = fmaxf(m[j].w, vs.w * rv.w);
            }
            rsp = rsc; rsc = rsn;
        }
    }

    // Sparse re-injection + store
    const float* spb = sparse + (size_t)b * PLANE;
    float*       ddb = ddst   + (size_t)b * PLANE;
    #pragma unroll
    for (int j = 0; j < BANDH; j++) {
        const int y = y0 + j;
        const float4 s = *reinterpret_cast<const float4*>(spb + (size_t)y * WW + x0);
        float4 v = m[j];
        v.x = (s.x > 0.f) ? s.x : v.x;
        v.y = (s.y > 0.f) ? s.y : v.y;
        v.z = (s.z > 0.f) ? s.z : v.z;
        v.w = (s.w > 0.f) ? s.w : v.w;
        *reinterpret_cast<float4*>(ddb + (size_t)y * WW + x0) = v;
    }
}

extern "C" void kernel_launch(void* const* d_in, const int* in_sizes, int n_in,
                              void* d_out, int out_size)
{
    const float* guid   = (const float*)d_in[0];
    const float* blur   = (const float*)d_in[1];
    const float* sparse = (const float*)d_in[2];
    float*       out    = (float*)d_out;

    precompute_kernel<<<NBANDS, 128>>>(guid, blur, sparse);

    // d0 lives in d_bufA. Even i reads A writes B, odd i reads B writes A.
    for (int i = 0; i < NITER; i++) {
        float* dst_ext = (i == NITER - 1) ? out : nullptr;
        iter_kernel<<<NBANDS, 128>>>(i & 1, dst_ext, sparse);
    }
}

// round 2
// speedup vs baseline: 1.2048x; 1.2048x over previous
#include <cuda_runtime.h>
#include <math.h>

#define BB 8
#define CC 8
#define HH 256
#define WW 512
#define PLANE (HH*WW)
#define NPIX (BB*PLANE)
#define BANDH 4
#define NROWS (BANDH+2)
#define NBANDS ((BB*HH)/BANDH)     /* 512 */
#define NXCH 2                      /* two 256-col chunks */
#define GRID (NBANDS*NXCH)          /* 1024 CTAs */
#define NITER 16
#define FULLMASK 0xffffffffu

// Scratch (allocation-free): gates, reciprocal weight-sums, depth ping-pong.
__device__ float g_buf[(size_t)BB*CC*PLANE];   // 32 MB
__device__ float r_buf[(size_t)BB*CC*PLANE];   // 32 MB
__device__ float d_bufA[NPIX];                 // 4 MB
__device__ float d_bufB[NPIX];                 // 4 MB

// ---------------------------------------------------------------------------
// Precompute: g = |guidance|, r = 1/(3x3 full sum of g), d0 = blend(blur,sparse)
// ---------------------------------------------------------------------------
__global__ __launch_bounds__(64, 12) void precompute_kernel(
    const float* __restrict__ guid,
    const float* __restrict__ blur,
    const float* __restrict__ sparse)
{
    const int lane  = threadIdx.x & 31;
    const int warp  = threadIdx.x >> 5;
    const int band  = blockIdx.x >> 1;
    const int chunk = blockIdx.x & 1;
    const int x0    = chunk * 256 + warp * 128 + lane * 4;
    const int b     = (band * BANDH) / HH;
    const int y0    = (band * BANDH) % HH;

    #pragma unroll 1
    for (int c = 0; c < CC; c++) {
        const float* gin  = guid  + ((size_t)(b * CC + c)) * PLANE;
        float*       gout = g_buf + ((size_t)(b * CC + c)) * PLANE;
        float*       rout = r_buf + ((size_t)(b * CC + c)) * PLANE;

        float4 rsp = make_float4(0.f, 0.f, 0.f, 0.f);
        float4 rsc = make_float4(0.f, 0.f, 0.f, 0.f);

        #pragma unroll
        for (int i = 0; i < NROWS; i++) {
            const int  ry    = y0 - 1 + i;
            const bool valid = (ry >= 0) && (ry < HH);

            float4 ga = make_float4(0.f, 0.f, 0.f, 0.f);
            if (valid) {
                const float4 gv = *reinterpret_cast<const float4*>(gin + (size_t)ry * WW + x0);
                ga.x = fabsf(gv.x); ga.y = fabsf(gv.y);
                ga.z = fabsf(gv.z); ga.w = fabsf(gv.w);
            }
            float gm1 = __shfl_up_sync  (FULLMASK, ga.w, 1);
            float gp4 = __shfl_down_sync(FULLMASK, ga.x, 1);
            if (lane == 0)  gm1 = (valid && x0 > 0)      ? fabsf(gin[(size_t)ry * WW + x0 - 1]) : 0.f;
            if (lane == 31) gp4 = (valid && x0 + 4 < WW) ? fabsf(gin[(size_t)ry * WW + x0 + 4]) : 0.f;

            float4 rsn;
            {
                const float t01 = ga.x + ga.y, t12 = ga.y + ga.z, t23 = ga.z + ga.w;
                rsn.x = gm1 + t01; rsn.y = t01 + ga.z;
                rsn.z = t12 + ga.w; rsn.w = t23 + gp4;
            }

            if (valid && ry >= y0 && ry < y0 + BANDH) {
                *reinterpret_cast<float4*>(gout + (size_t)ry * WW + x0) = ga;
            }

            if (i >= 2) {
                const int yo = y0 + i - 2;
                float4 vs;
                vs.x = rsp.x + rsc.x + rsn.x;
                vs.y = rsp.y + rsc.y + rsn.y;
                vs.z = rsp.z + rsc.z + rsn.z;
                vs.w = rsp.w + rsc.w + rsn.w;
                float4 rv;
                rv.x = 1.0f / vs.x; rv.y = 1.0f / vs.y;
                rv.z = 1.0f / vs.z; rv.w = 1.0f / vs.w;
                *reinterpret_cast<float4*>(rout + (size_t)yo * WW + x0) = rv;
            }
            rsp = rsc; rsc = rsn;
        }
    }

    // d0 = sparse > 0 ? sparse : blur
    const float* sp = sparse + (size_t)b * PLANE;
    const float* bl = blur   + (size_t)b * PLANE;
    float*       dd = d_bufA + (size_t)b * PLANE;
    #pragma unroll
    for (int j = 0; j < BANDH; j++) {
        const int y = y0 + j;
        float4 s = *reinterpret_cast<const float4*>(sp + (size_t)y * WW + x0);
        float4 v = *reinterpret_cast<const float4*>(bl + (size_t)y * WW + x0);
        v.x = (s.x > 0.f) ? s.x : v.x;
        v.y = (s.y > 0.f) ? s.y : v.y;
        v.z = (s.z > 0.f) ? s.z : v.z;
        v.w = (s.w > 0.f) ? s.w : v.w;
        *reinterpret_cast<float4*>(dd + (size_t)y * WW + x0) = v;
    }
}

// ---------------------------------------------------------------------------
// One CSPN step:
//   d_new(p) = max_c [ r[c](p) * sum_{3x3} g[c](n)*d(n) ] , then sparse blend.
// d band (incl. left/right halo) preloaded into registers once, reused for
// all 8 channels. Horizontal halo via shfl, vertical via rolling registers.
// ---------------------------------------------------------------------------
__global__ __launch_bounds__(64, 12) void iter_kernel(
    int src_sel,                    // 0: read d_bufA, 1: read d_bufB
    float* __restrict__ dst_ext,    // if non-null, write here (final iter)
    const float* __restrict__ sparse)
{
    const int lane  = threadIdx.x & 31;
    const int warp  = threadIdx.x >> 5;
    const int band  = blockIdx.x >> 1;
    const int chunk = blockIdx.x & 1;
    const int x0    = chunk * 256 + warp * 128 + lane * 4;
    const int b     = (band * BANDH) / HH;
    const int y0    = (band * BANDH) % HH;

    const float* dsrc = src_sel ? d_bufB : d_bufA;
    float*       ddst = dst_ext ? dst_ext : (src_sel ? d_bufA : d_bufB);
    const float* dsb  = dsrc + (size_t)b * PLANE;

    // ---- Preload d band (rows y0-1 .. y0+BANDH) with horizontal halo ----
    float4 dv [NROWS];
    float  dm1[NROWS];
    float  dp4[NROWS];
    #pragma unroll
    for (int i = 0; i < NROWS; i++) {
        const int  ry    = y0 - 1 + i;
        const bool valid = (ry >= 0) && (ry < HH);
        float4 v = make_float4(0.f, 0.f, 0.f, 0.f);
        if (valid) v = *reinterpret_cast<const float4*>(dsb + (size_t)ry * WW + x0);
        float l = __shfl_up_sync  (FULLMASK, v.w, 1);
        float r = __shfl_down_sync(FULLMASK, v.x, 1);
        if (lane == 0)  l = (valid && x0 > 0)      ? dsb[(size_t)ry * WW + x0 - 1] : 0.f;
        if (lane == 31) r = (valid && x0 + 4 < WW) ? dsb[(size_t)ry * WW + x0 + 4] : 0.f;
        dv[i] = v; dm1[i] = l; dp4[i] = r;
    }

    float4 m[BANDH];
    #pragma unroll
    for (int j = 0; j < BANDH; j++) m[j] = make_float4(0.f, 0.f, 0.f, 0.f);

    #pragma unroll 1
    for (int c = 0; c < CC; c++) {
        const float* gc = g_buf + ((size_t)(b * CC + c)) * PLANE;
        const float* rc = r_buf + ((size_t)(b * CC + c)) * PLANE;

        float4 rsp = make_float4(0.f, 0.f, 0.f, 0.f);
        float4 rsc = make_float4(0.f, 0.f, 0.f, 0.f);

        #pragma unroll
        for (int i = 0; i < NROWS; i++) {
            const int  ry    = y0 - 1 + i;
            const bool valid = (ry >= 0) && (ry < HH);

            float4 gv = make_float4(0.f, 0.f, 0.f, 0.f);
            if (valid) gv = *reinterpret_cast<const float4*>(gc + (size_t)ry * WW + x0);
            float gm1 = __shfl_up_sync  (FULLMASK, gv.w, 1);
            float gp4 = __shfl_down_sync(FULLMASK, gv.x, 1);
            if (lane == 0)  gm1 = (valid && x0 > 0)      ? gc[(size_t)ry * WW + x0 - 1] : 0.f;
            if (lane == 31) gp4 = (valid && x0 + 4 < WW) ? gc[(size_t)ry * WW + x0 + 4] : 0.f;

            const float um1 = gm1  * dm1[i];
            const float u0  = gv.x * dv[i].x;
            const float u1  = gv.y * dv[i].y;
            const float u2  = gv.z * dv[i].z;
            const float u3  = gv.w * dv[i].w;
            const float up4 = gp4  * dp4[i];

            float4 rsn;
            {
                const float t01 = u0 + u1, t12 = u1 + u2, t23 = u2 + u3;
                rsn.x = um1 + t01; rsn.y = t01 + u2;
                rsn.z = t12 + u3;  rsn.w = t23 + up4;
            }

            if (i >= 2) {
                const int yo = y0 + i - 2;
                const float4 rv = *reinterpret_cast<const float4*>(rc + (size_t)yo * WW + x0);
                float4 vs;
                vs.x = rsp.x + rsc.x + rsn.x;
                vs.y = rsp.y + rsc.y + rsn.y;
                vs.z = rsp.z + rsc.z + rsn.z;
                vs.w = rsp.w + rsc.w + rsn.w;
                const int j = i - 2;
                m[j].x = fmaxf(m[j].x, vs.x * rv.x);
                m[j].y = fmaxf(m[j].y, vs.y * rv.y);
                m[j].z = fmaxf(m[j].z, vs.z * rv.z);
                m[j].w = fmaxf(m[j].w, vs.w * rv.w);
            }
            rsp = rsc; rsc = rsn;
        }
    }

    // Sparse re-injection + store
    const float* spb = sparse + (size_t)b * PLANE;
    float*       ddb = ddst   + (size_t)b * PLANE;
    #pragma unroll
    for (int j = 0; j < BANDH; j++) {
        const int y = y0 + j;
        const float4 s = *reinterpret_cast<const float4*>(spb + (size_t)y * WW + x0);
        float4 v = m[j];
        v.x = (s.x > 0.f) ? s.x : v.x;
        v.y = (s.y > 0.f) ? s.y : v.y;
        v.z = (s.z > 0.f) ? s.z : v.z;
        v.w = (s.w > 0.f) ? s.w : v.w;
        *reinterpret_cast<float4*>(ddb + (size_t)y * WW + x0) = v;
    }
}

extern "C" void kernel_launch(void* const* d_in, const int* in_sizes, int n_in,
                              void* d_out, int out_size)
{
    const float* guid   = (const float*)d_in[0];
    const float* blur   = (const float*)d_in[1];
    const float* sparse = (const float*)d_in[2];
    float*       out    = (float*)d_out;

    precompute_kernel<<<GRID, 64>>>(guid, blur, sparse);

    // d0 lives in d_bufA. Even i reads A writes B, odd i reads B writes A.
    for (int i = 0; i < NITER; i++) {
        float* dst_ext = (i == NITER - 1) ? out : nullptr;
        iter_kernel<<<GRID, 64>>>(i & 1, dst_ext, sparse);
    }
}

// round 3
// speedup vs baseline: 1.4254x; 1.1831x over previous
#include <cuda_runtime.h>
#include <math.h>

#define BB 8
#define CC 8
#define HH 256
#define WW 512
#define PLANE (HH*WW)
#define NPIX (BB*PLANE)
#define BANDH 4
#define NROWS (BANDH+2)
#define TX 128                       /* cols per iter CTA */
#define GRID_I (BB*(HH/BANDH)*(WW/TX))   /* 8*64*4 = 2048 */
#define NBANDS ((BB*HH)/BANDH)       /* 512 */
#define GRID_P (NBANDS*2*CC)         /* 8192: channel parallel precompute */
#define NITER 16
#define FULLMASK 0xffffffffu

// Scratch (allocation-free): gates, reciprocal weight-sums, depth ping-pong.
__device__ float g_buf[(size_t)BB*CC*PLANE];   // 32 MB
__device__ float r_buf[(size_t)BB*CC*PLANE];   // 32 MB
__device__ float d_bufA[NPIX];                 // 4 MB
__device__ float d_bufB[NPIX];                 // 4 MB

// ---------------------------------------------------------------------------
// Precompute: g = |guidance|, r = 1/(3x3 full sum of g), d0 = blend(blur,sparse)
// One CTA per (channel, band, chunk) — channels parallel across blocks.
// ---------------------------------------------------------------------------
__global__ __launch_bounds__(64) void precompute_kernel(
    const float* __restrict__ guid,
    const float* __restrict__ blur,
    const float* __restrict__ sparse)
{
    const int lane  = threadIdx.x & 31;
    const int warp  = threadIdx.x >> 5;
    const int c     = blockIdx.x >> 10;        // 0..7
    const int inner = blockIdx.x & 1023;
    const int band  = inner >> 1;              // 0..511
    const int chunk = inner & 1;
    const int x0    = chunk * 256 + warp * 128 + lane * 4;
    const int b     = (band * BANDH) / HH;
    const int y0    = (band * BANDH) % HH;

    {
        const float* gin  = guid  + ((size_t)(b * CC + c)) * PLANE;
        float*       gout = g_buf + ((size_t)(b * CC + c)) * PLANE;
        float*       rout = r_buf + ((size_t)(b * CC + c)) * PLANE;

        float4 rsp = make_float4(0.f, 0.f, 0.f, 0.f);
        float4 rsc = make_float4(0.f, 0.f, 0.f, 0.f);

        #pragma unroll
        for (int i = 0; i < NROWS; i++) {
            const int  ry    = y0 - 1 + i;
            const bool valid = (ry >= 0) && (ry < HH);

            float4 ga = make_float4(0.f, 0.f, 0.f, 0.f);
            if (valid) {
                const float4 gv = *reinterpret_cast<const float4*>(gin + (size_t)ry * WW + x0);
                ga.x = fabsf(gv.x); ga.y = fabsf(gv.y);
                ga.z = fabsf(gv.z); ga.w = fabsf(gv.w);
            }
            float gm1 = __shfl_up_sync  (FULLMASK, ga.w, 1);
            float gp4 = __shfl_down_sync(FULLMASK, ga.x, 1);
            if (lane == 0)  gm1 = (valid && x0 > 0)      ? fabsf(gin[(size_t)ry * WW + x0 - 1]) : 0.f;
            if (lane == 31) gp4 = (valid && x0 + 4 < WW) ? fabsf(gin[(size_t)ry * WW + x0 + 4]) : 0.f;

            float4 rsn;
            {
                const float t01 = ga.x + ga.y, t12 = ga.y + ga.z, t23 = ga.z + ga.w;
                rsn.x = gm1 + t01; rsn.y = t01 + ga.z;
                rsn.z = t12 + ga.w; rsn.w = t23 + gp4;
            }

            if (valid && ry >= y0 && ry < y0 + BANDH) {
                *reinterpret_cast<float4*>(gout + (size_t)ry * WW + x0) = ga;
            }

            if (i >= 2) {
                const int yo = y0 + i - 2;
                float4 vs;
                vs.x = rsp.x + rsc.x + rsn.x;
                vs.y = rsp.y + rsc.y + rsn.y;
                vs.z = rsp.z + rsc.z + rsn.z;
                vs.w = rsp.w + rsc.w + rsn.w;
                float4 rv;
                rv.x = 1.0f / vs.x; rv.y = 1.0f / vs.y;
                rv.z = 1.0f / vs.z; rv.w = 1.0f / vs.w;
                *reinterpret_cast<float4*>(rout + (size_t)yo * WW + x0) = rv;
            }
            rsp = rsc; rsc = rsn;
        }
    }

    // d0 = sparse > 0 ? sparse : blur  (channel-0 CTAs only)
    if (c == 0) {
        const float* sp = sparse + (size_t)b * PLANE;
        const float* bl = blur   + (size_t)b * PLANE;
        float*       dd = d_bufA + (size_t)b * PLANE;
        #pragma unroll
        for (int j = 0; j < BANDH; j++) {
            const int y = y0 + j;
            float4 s = *reinterpret_cast<const float4*>(sp + (size_t)y * WW + x0);
            float4 v = *reinterpret_cast<const float4*>(bl + (size_t)y * WW + x0);
            v.x = (s.x > 0.f) ? s.x : v.x;
            v.y = (s.y > 0.f) ? s.y : v.y;
            v.z = (s.z > 0.f) ? s.z : v.z;
            v.w = (s.w > 0.f) ? s.w : v.w;
            *reinterpret_cast<float4*>(dd + (size_t)y * WW + x0) = v;
        }
    }
}

// ---------------------------------------------------------------------------
// One CSPN step. 8 warps/CTA, one gate channel per warp over a 4x128 tile.
// d band shared via smem, per-channel results max-reduced via smem.
// ---------------------------------------------------------------------------
__global__ __launch_bounds__(256) void iter_kernel(
    int src_sel,                    // 0: read d_bufA, 1: read d_bufB
    float* __restrict__ dst_ext,    // if non-null, write here (final iter)
    const float* __restrict__ sparse)
{
    __shared__ float4 sd4[NROWS][TX/4];        // d band, 6 x 32 float4
    __shared__ float  sl[NROWS], sr[NROWS];    // L/R halo columns
    __shared__ float  souts[CC][BANDH][TX];    // per-channel results, 16 KB

    const int tid  = threadIdx.x;
    const int lane = tid & 31;
    const int c    = tid >> 5;                 // warp == channel
    const int bid  = blockIdx.x;
    const int xc   = bid & 3;
    const int yb   = (bid >> 2) & 63;
    const int b    = bid >> 8;
    const int x0   = xc * TX;
    const int y0   = yb * BANDH;

    const float* dsrc = src_sel ? d_bufB : d_bufA;
    float*       ddst = dst_ext ? dst_ext : (src_sel ? d_bufA : d_bufB);
    const float* dsb  = dsrc + (size_t)b * PLANE;

    // ---- cooperative load of d band into smem ----
    #pragma unroll
    for (int idx = tid; idx < NROWS * TX; idx += 256) {
        const int row = idx >> 7;
        const int col = idx & 127;
        const int gy  = y0 - 1 + row;
        float v = 0.f;
        if (gy >= 0 && gy < HH) v = dsb[(size_t)gy * WW + x0 + col];
        reinterpret_cast<float*>(sd4)[row * TX + col] = v;
    }
    if (tid < NROWS) {
        const int gy = y0 - 1 + tid;
        const bool vy = (gy >= 0) && (gy < HH);
        sl[tid] = (vy && x0 > 0)       ? dsb[(size_t)gy * WW + x0 - 1]  : 0.f;
        sr[tid] = (vy && x0 + TX < WW) ? dsb[(size_t)gy * WW + x0 + TX] : 0.f;
    }
    __syncthreads();

    // ---- per-warp register copy of d band (with horizontal halo) ----
    float4 dv[NROWS]; float dm1[NROWS], dp4[NROWS];
    #pragma unroll
    for (int i = 0; i < NROWS; i++) {
        const float4 v = sd4[i][lane];
        float l = __shfl_up_sync  (FULLMASK, v.w, 1);
        float r = __shfl_down_sync(FULLMASK, v.x, 1);
        if (lane == 0)  l = sl[i];
        if (lane == 31) r = sr[i];
        dv[i] = v; dm1[i] = l; dp4[i] = r;
    }

    // ---- this warp's channel ----
    const float* gc = g_buf + ((size_t)(b * CC + c)) * PLANE;
    const float* rc = r_buf + ((size_t)(b * CC + c)) * PLANE;
    const int lx = x0 + lane * 4;

    float4 rsp = make_float4(0.f,0.f,0.f,0.f);
    float4 rsc = make_float4(0.f,0.f,0.f,0.f);

    #pragma unroll
    for (int i = 0; i < NROWS; i++) {
        const int  ry    = y0 - 1 + i;
        const bool valid = (ry >= 0) && (ry < HH);

        float4 gv = make_float4(0.f, 0.f, 0.f, 0.f);
        if (valid) gv = *reinterpret_cast<const float4*>(gc + (size_t)ry * WW + lx);
        float gm1 = __shfl_up_sync  (FULLMASK, gv.w, 1);
        float gp4 = __shfl_down_sync(FULLMASK, gv.x, 1);
        if (lane == 0)  gm1 = (valid && lx > 0)      ? gc[(size_t)ry * WW + lx - 1] : 0.f;
        if (lane == 31) gp4 = (valid && lx + 4 < WW) ? gc[(size_t)ry * WW + lx + 4] : 0.f;

        const float um1 = gm1  * dm1[i];
        const float u0  = gv.x * dv[i].x;
        const float u1  = gv.y * dv[i].y;
        const float u2  = gv.z * dv[i].z;
        const float u3  = gv.w * dv[i].w;
        const float up4 = gp4  * dp4[i];

        float4 rsn;
        {
            const float t01 = u0 + u1, t12 = u1 + u2, t23 = u2 + u3;
            rsn.x = um1 + t01; rsn.y = t01 + u2;
            rsn.z = t12 + u3;  rsn.w = t23 + up4;
        }

        if (i >= 2) {
            const int yo = y0 + i - 2;
            const float4 rv = *reinterpret_cast<const float4*>(rc + (size_t)yo * WW + lx);
            float4 o;
            o.x = (rsp.x + rsc.x + rsn.x) * rv.x;
            o.y = (rsp.y + rsc.y + rsn.y) * rv.y;
            o.z = (rsp.z + rsc.z + rsn.z) * rv.z;
            o.w = (rsp.w + rsc.w + rsn.w) * rv.w;
            *reinterpret_cast<float4*>(&souts[c][i - 2][lane * 4]) = o;
        }
        rsp = rsc; rsc = rsn;
    }
    __syncthreads();

    // ---- 8-way max reduce + sparse re-injection + coalesced store ----
    const float* spb = sparse + (size_t)b * PLANE;
    float*       ddb = ddst   + (size_t)b * PLANE;
    #pragma unroll
    for (int idx = tid; idx < BANDH * TX; idx += 256) {
        const int row = idx >> 7;
        const int col = idx & 127;
        float m = souts[0][row][col];
        #pragma unroll
        for (int cc = 1; cc < CC; cc++) m = fmaxf(m, souts[cc][row][col]);
        const size_t off = (size_t)(y0 + row) * WW + x0 + col;
        const float s = spb[off];
        ddb[off] = (s > 0.f) ? s : m;
    }
}

extern "C" void kernel_launch(void* const* d_in, const int* in_sizes, int n_in,
                              void* d_out, int out_size)
{
    const float* guid   = (const float*)d_in[0];
    const float* blur   = (const float*)d_in[1];
    const float* sparse = (const float*)d_in[2];
    float*       out    = (float*)d_out;

    precompute_kernel<<<GRID_P, 64>>>(guid, blur, sparse);

    // d0 lives in d_bufA. Even i reads A writes B, odd i reads B writes A.
    for (int i = 0; i < NITER; i++) {
        float* dst_ext = (i == NITER - 1) ? out : nullptr;
        iter_kernel<<<GRID_I, 256>>>(i & 1, dst_ext, sparse);
    }
}

// round 4
// speedup vs baseline: 1.4606x; 1.0247x over previous
#include <cuda_runtime.h>
#include <math.h>

#define BB 8
#define CC 8
#define HH 256
#define WW 512
#define PLANE (HH*WW)
#define NPIX (BB*PLANE)
#define BANDH 4
#define NROWS (BANDH+2)
#define TX 128                            /* cols per iter CTA */
#define GRID_I (BB*(HH/BANDH)*(WW/TX))    /* 8*64*4 = 2048 */
#define NITER 16
#define FULLMASK 0xffffffffu

// Depth ping-pong scratch (allocation-free).
__device__ float d_bufA[NPIX];            // 4 MB
__device__ float d_bufB[NPIX];            // 4 MB

// ---------------------------------------------------------------------------
// Init: d0 = sparse > 0 ? sparse : blur   (pure elementwise)
// ---------------------------------------------------------------------------
__global__ __launch_bounds__(256) void init_kernel(
    const float* __restrict__ blur,
    const float* __restrict__ sparse)
{
    const int i = blockIdx.x * 256 + threadIdx.x;   // float4 index
    const float4 s = reinterpret_cast<const float4*>(sparse)[i];
    float4 v       = reinterpret_cast<const float4*>(blur)[i];
    v.x = (s.x > 0.f) ? s.x : v.x;
    v.y = (s.y > 0.f) ? s.y : v.y;
    v.z = (s.z > 0.f) ? s.z : v.z;
    v.w = (s.w > 0.f) ? s.w : v.w;
    reinterpret_cast<float4*>(d_bufA)[i] = v;
}

// ---------------------------------------------------------------------------
// One CSPN step:
//   d_new(p) = max_c [ sum_{3x3} g_c(n) d(n) / sum_{3x3} g_c(n) ],  g = |guid|
//   then sparse re-injection.
// 8 warps/CTA, one gate channel per warp over a 4x128 tile.
// g read straight from guidance (fabs fused into FMUL operand); wsum computed
// on the fly from the same g rows (no r buffer, no g buffer).
// ---------------------------------------------------------------------------
__global__ __launch_bounds__(256) void iter_kernel(
    int src_sel,                    // 0: read d_bufA, 1: read d_bufB
    float* __restrict__ dst_ext,    // if non-null, write here (final iter)
    const float* __restrict__ guid,
    const float* __restrict__ sparse)
{
    __shared__ float4 sd4[NROWS][TX/4];        // d band, 6 x 32 float4
    __shared__ float  sl[NROWS], sr[NROWS];    // L/R halo columns
    __shared__ float  souts[CC][BANDH][TX];    // per-channel results, 16 KB

    const int tid  = threadIdx.x;
    const int lane = tid & 31;
    const int c    = tid >> 5;                 // warp == channel
    const int bid  = blockIdx.x;
    const int xc   = bid & 3;
    const int yb   = (bid >> 2) & 63;
    const int b    = bid >> 8;
    const int x0   = xc * TX;
    const int y0   = yb * BANDH;

    const float* dsrc = src_sel ? d_bufB : d_bufA;
    float*       ddst = dst_ext ? dst_ext : (src_sel ? d_bufA : d_bufB);
    const float* dsb  = dsrc + (size_t)b * PLANE;

    // ---- cooperative vectorized load of d band into smem ----
    if (tid < NROWS * (TX/4)) {
        const int row = tid >> 5;              // /32
        const int c4  = tid & 31;
        const int gy  = y0 - 1 + row;
        float4 v = make_float4(0.f, 0.f, 0.f, 0.f);
        if (gy >= 0 && gy < HH)
            v = *reinterpret_cast<const float4*>(dsb + (size_t)gy * WW + x0 + c4 * 4);
        sd4[row][c4] = v;
    }
    if (tid >= 224 && tid < 224 + NROWS) {     // separate warp does edges
        const int i  = tid - 224;
        const int gy = y0 - 1 + i;
        const bool vy = (gy >= 0) && (gy < HH);
        sl[i] = (vy && x0 > 0)       ? dsb[(size_t)gy * WW + x0 - 1]  : 0.f;
        sr[i] = (vy && x0 + TX < WW) ? dsb[(size_t)gy * WW + x0 + TX] : 0.f;
    }
    __syncthreads();

    // ---- per-warp register copy of d band (with horizontal halo) ----
    float4 dv[NROWS]; float dm1[NROWS], dp4[NROWS];
    #pragma unroll
    for (int i = 0; i < NROWS; i++) {
        const float4 v = sd4[i][lane];
        float l = __shfl_up_sync  (FULLMASK, v.w, 1);
        float r = __shfl_down_sync(FULLMASK, v.x, 1);
        if (lane == 0)  l = sl[i];
        if (lane == 31) r = sr[i];
        dv[i] = v; dm1[i] = l; dp4[i] = r;
    }

    // ---- this warp's channel: numerator + weight rowsums, rolling vertical ----
    const float* gc = guid + ((size_t)(b * CC + c)) * PLANE;
    const int lx = x0 + lane * 4;

    float4 usp = make_float4(0.f,0.f,0.f,0.f), usc = usp;  // u = g*d rowsums
    float4 gsp = make_float4(0.f,0.f,0.f,0.f), gsc = gsp;  // g rowsums

    #pragma unroll
    for (int i = 0; i < NROWS; i++) {
        const int  ry    = y0 - 1 + i;
        const bool valid = (ry >= 0) && (ry < HH);

        float4 gr = make_float4(0.f, 0.f, 0.f, 0.f);
        if (valid) gr = *reinterpret_cast<const float4*>(gc + (size_t)ry * WW + lx);
        float4 ga;
        ga.x = fabsf(gr.x); ga.y = fabsf(gr.y);
        ga.z = fabsf(gr.z); ga.w = fabsf(gr.w);
        float gm1 = __shfl_up_sync  (FULLMASK, ga.w, 1);
        float gp4 = __shfl_down_sync(FULLMASK, ga.x, 1);
        if (lane == 0)  gm1 = (valid && lx > 0)      ? fabsf(gc[(size_t)ry * WW + lx - 1]) : 0.f;
        if (lane == 31) gp4 = (valid && lx + 4 < WW) ? fabsf(gc[(size_t)ry * WW + lx + 4]) : 0.f;

        const float um1 = gm1  * dm1[i];
        const float u0  = ga.x * dv[i].x;
        const float u1  = ga.y * dv[i].y;
        const float u2  = ga.z * dv[i].z;
        const float u3  = ga.w * dv[i].w;
        const float up4 = gp4  * dp4[i];

        float4 usn, gsn;
        {
            const float t01 = u0 + u1, t12 = u1 + u2, t23 = u2 + u3;
            usn.x = um1 + t01; usn.y = t01 + u2;
            usn.z = t12 + u3;  usn.w = t23 + up4;
            const float s01 = ga.x + ga.y, s12 = ga.y + ga.z, s23 = ga.z + ga.w;
            gsn.x = gm1 + s01; gsn.y = s01 + ga.z;
            gsn.z = s12 + ga.w; gsn.w = s23 + gp4;
        }

        if (i >= 2) {
            float4 o;
            o.x = __fdividef(usp.x + usc.x + usn.x, gsp.x + gsc.x + gsn.x);
            o.y = __fdividef(usp.y + usc.y + usn.y, gsp.y + gsc.y + gsn.y);
            o.z = __fdividef(usp.z + usc.z + usn.z, gsp.z + gsc.z + gsn.z);
            o.w = __fdividef(usp.w + usc.w + usn.w, gsp.w + gsc.w + gsn.w);
            *reinterpret_cast<float4*>(&souts[c][i - 2][lane * 4]) = o;
        }
        usp = usc; usc = usn;
        gsp = gsc; gsc = gsn;
    }
    __syncthreads();

    // ---- 8-way max reduce + sparse re-injection + coalesced store ----
    const float* spb = sparse + (size_t)b * PLANE;
    float*       ddb = ddst   + (size_t)b * PLANE;
    #pragma unroll
    for (int idx = tid; idx < BANDH * TX; idx += 256) {
        const int row = idx >> 7;
        const int col = idx & 127;
        float m = souts[0][row][col];
        #pragma unroll
        for (int cc = 1; cc < CC; cc++) m = fmaxf(m, souts[cc][row][col]);
        const size_t off = (size_t)(y0 + row) * WW + x0 + col;
        const float s = spb[off];
        ddb[off] = (s > 0.f) ? s : m;
    }
}

extern "C" void kernel_launch(void* const* d_in, const int* in_sizes, int n_in,
                              void* d_out, int out_size)
{
    const float* guid   = (const float*)d_in[0];
    const float* blur   = (const float*)d_in[1];
    const float* sparse = (const float*)d_in[2];
    float*       out    = (float*)d_out;

    init_kernel<<<NPIX / 4 / 256, 256>>>(blur, sparse);

    // d0 lives in d_bufA. Even i reads A writes B, odd i reads B writes A.
    for (int i = 0; i < NITER; i++) {
        float* dst_ext = (i == NITER - 1) ? out : nullptr;
        iter_kernel<<<GRID_I, 256>>>(i & 1, dst_ext, guid, sparse);
    }
}

// round 5
// speedup vs baseline: 1.7306x; 1.1849x over previous
#include <cuda_runtime.h>
#include <math.h>

#define BB 8
#define CC 8
#define HH 256
#define WW 512
#define PLANE (HH*WW)
#define NPIX (BB*PLANE)
#define BANDH 4
#define NROWS (BANDH+2)
#define TX 128                            /* cols per iter CTA */
#define GRID_I (BB*(HH/BANDH)*(WW/TX))    /* 8*64*4 = 2048 */
#define NITER 16
#define FULLMASK 0xffffffffu

// Depth ping-pong scratch (allocation-free).
__device__ float d_bufA[NPIX];            // 4 MB
__device__ float d_bufB[NPIX];            // 4 MB

// ---------------------------------------------------------------------------
// Init: d0 = sparse > 0 ? sparse : blur   (pure elementwise)
// ---------------------------------------------------------------------------
__global__ __launch_bounds__(256) void init_kernel(
    const float* __restrict__ blur,
    const float* __restrict__ sparse)
{
    const int i = blockIdx.x * 256 + threadIdx.x;   // float4 index
    const float4 s = reinterpret_cast<const float4*>(sparse)[i];
    float4 v       = reinterpret_cast<const float4*>(blur)[i];
    v.x = (s.x > 0.f) ? s.x : v.x;
    v.y = (s.y > 0.f) ? s.y : v.y;
    v.z = (s.z > 0.f) ? s.z : v.z;
    v.w = (s.w > 0.f) ? s.w : v.w;
    reinterpret_cast<float4*>(d_bufA)[i] = v;
}

// ---------------------------------------------------------------------------
// One CSPN step:
//   d_new(p) = max_c [ sum_{3x3} g_c(n) d(n) / sum_{3x3} g_c(n) ],  g = |guid|
//   then sparse re-injection.
// 8 warps/CTA = 8 gate channels over a 4x128 tile. Each warp loads its g band
// AND the shared d band directly from global (d lines L1-hit across warps),
// so there is no producer barrier — only one sync before the 8-way reduce.
// ---------------------------------------------------------------------------
__global__ __launch_bounds__(256, 4) void iter_kernel(
    int src_sel,                    // 0: read d_bufA, 1: read d_bufB
    float* __restrict__ dst_ext,    // if non-null, write here (final iter)
    const float* __restrict__ guid,
    const float* __restrict__ sparse)
{
    __shared__ float souts[CC][BANDH][TX]; // per-channel results, 16 KB

    const int tid  = threadIdx.x;
    const int lane = tid & 31;
    const int c    = tid >> 5;             // warp == channel
    const int bid  = blockIdx.x;
    const int xc   = bid & 3;
    const int yb   = (bid >> 2) & 63;
    const int b    = bid >> 8;
    const int x0   = xc * TX;
    const int y0   = yb * BANDH;

    const float* dsrc = src_sel ? d_bufB : d_bufA;
    float*       ddst = dst_ext ? dst_ext : (src_sel ? d_bufA : d_bufB);
    const float* dsb  = dsrc   + (size_t)b * PLANE;
    const float* spb  = sparse + (size_t)b * PLANE;
    float*       ddb  = ddst   + (size_t)b * PLANE;

    // ---- prefetch sparse for the epilogue (independent of everything) ----
    float4 sp_pre = make_float4(0.f, 0.f, 0.f, 0.f);
    int    ep_row = 0, ep_c4 = 0;
    if (tid < BANDH * (TX / 4)) {          // 128 threads
        ep_row = tid >> 5;
        ep_c4  = tid & 31;
        sp_pre = *reinterpret_cast<const float4*>(
                     spb + (size_t)(y0 + ep_row) * WW + x0 + ep_c4 * 4);
    }

    // ---- this warp's channel: stream 6 rows, rolling vertical sums ----
    const float* gc = guid + ((size_t)(b * CC + c)) * PLANE;
    const int lx = x0 + lane * 4;

    float4 usp = make_float4(0.f,0.f,0.f,0.f), usc = usp;  // u = g*d rowsums
    float4 gsp = make_float4(0.f,0.f,0.f,0.f), gsc = gsp;  // g rowsums

    #pragma unroll
    for (int i = 0; i < NROWS; i++) {
        const int  ry    = y0 - 1 + i;
        const bool valid = (ry >= 0) && (ry < HH);

        float4 gr = make_float4(0.f, 0.f, 0.f, 0.f);
        float4 dr = make_float4(0.f, 0.f, 0.f, 0.f);
        if (valid) {
            gr = *reinterpret_cast<const float4*>(gc  + (size_t)ry * WW + lx);
            dr = *reinterpret_cast<const float4*>(dsb + (size_t)ry * WW + lx);
        }
        float4 ga;
        ga.x = fabsf(gr.x); ga.y = fabsf(gr.y);
        ga.z = fabsf(gr.z); ga.w = fabsf(gr.w);

        float gm1 = __shfl_up_sync  (FULLMASK, ga.w, 1);
        float dm1 = __shfl_up_sync  (FULLMASK, dr.w, 1);
        float gp4 = __shfl_down_sync(FULLMASK, ga.x, 1);
        float dp4 = __shfl_down_sync(FULLMASK, dr.x, 1);
        if (lane == 0) {
            const bool e = valid && (lx > 0);
            gm1 = e ? fabsf(gc[(size_t)ry * WW + lx - 1]) : 0.f;
            dm1 = e ?       dsb[(size_t)ry * WW + lx - 1] : 0.f;
        }
        if (lane == 31) {
            const bool e = valid && (lx + 4 < WW);
            gp4 = e ? fabsf(gc[(size_t)ry * WW + lx + 4]) : 0.f;
            dp4 = e ?       dsb[(size_t)ry * WW + lx + 4] : 0.f;
        }

        const float um1 = gm1  * dm1;
        const float u0  = ga.x * dr.x;
        const float u1  = ga.y * dr.y;
        const float u2  = ga.z * dr.z;
        const float u3  = ga.w * dr.w;
        const float up4 = gp4  * dp4;

        float4 usn, gsn;
        {
            const float t01 = u0 + u1, t12 = u1 + u2, t23 = u2 + u3;
            usn.x = um1 + t01; usn.y = t01 + u2;
            usn.z = t12 + u3;  usn.w = t23 + up4;
            const float s01 = ga.x + ga.y, s12 = ga.y + ga.z, s23 = ga.z + ga.w;
            gsn.x = gm1 + s01;  gsn.y = s01 + ga.z;
            gsn.z = s12 + ga.w; gsn.w = s23 + gp4;
        }

        if (i >= 2) {
            float4 o;
            o.x = __fdividef(usp.x + usc.x + usn.x, gsp.x + gsc.x + gsn.x);
            o.y = __fdividef(usp.y + usc.y + usn.y, gsp.y + gsc.y + gsn.y);
            o.z = __fdividef(usp.z + usc.z + usn.z, gsp.z + gsc.z + gsn.z);
            o.w = __fdividef(usp.w + usc.w + usn.w, gsp.w + gsc.w + gsn.w);
            *reinterpret_cast<float4*>(&souts[c][i - 2][lane * 4]) = o;
        }
        usp = usc; usc = usn;
        gsp = gsc; gsc = gsn;
    }
    __syncthreads();

    // ---- 8-way max reduce + sparse re-injection + float4 store ----
    if (tid < BANDH * (TX / 4)) {
        float4 m = *reinterpret_cast<const float4*>(&souts[0][ep_row][ep_c4 * 4]);
        #pragma unroll
        for (int cc = 1; cc < CC; cc++) {
            const float4 v = *reinterpret_cast<const float4*>(&souts[cc][ep_row][ep_c4 * 4]);
            m.x = fmaxf(m.x, v.x); m.y = fmaxf(m.y, v.y);
            m.z = fmaxf(m.z, v.z); m.w = fmaxf(m.w, v.w);
        }
        m.x = (sp_pre.x > 0.f) ? sp_pre.x : m.x;
        m.y = (sp_pre.y > 0.f) ? sp_pre.y : m.y;
        m.z = (sp_pre.z > 0.f) ? sp_pre.z : m.z;
        m.w = (sp_pre.w > 0.f) ? sp_pre.w : m.w;
        *reinterpret_cast<float4*>(ddb + (size_t)(y0 + ep_row) * WW + x0 + ep_c4 * 4) = m;
    }
}

extern "C" void kernel_launch(void* const* d_in, const int* in_sizes, int n_in,
                              void* d_out, int out_size)
{
    const float* guid   = (const float*)d_in[0];
    const float* blur   = (const float*)d_in[1];
    const float* sparse = (const float*)d_in[2];
    float*       out    = (float*)d_out;

    init_kernel<<<NPIX / 4 / 256, 256>>>(blur, sparse);

    // d0 lives in d_bufA. Even i reads A writes B, odd i reads B writes A.
    for (int i = 0; i < NITER; i++) {
        float* dst_ext = (i == NITER - 1) ? out : nullptr;
        iter_kernel<<<GRID_I, 256>>>(i & 1, dst_ext, guid, sparse);
    }
}

// round 6
// speedup vs baseline: 2.3345x; 1.3490x over previous
#include <cuda_runtime.h>
#include <math.h>

#define BB 8
#define CC 8
#define HH 256
#define WW 512
#define PLANE (HH*WW)
#define NPIX (BB*PLANE)
#define BANDH 8
#define NROWS (BANDH+2)
#define TX 128                            /* cols per iter CTA */
#define GRID_I (BB*(HH/BANDH)*(WW/TX))    /* 8*32*4 = 1024 */
#define NITER 16
#define FULLMASK 0xffffffffu

// Depth ping-pong scratch (allocation-free).
__device__ float d_bufA[NPIX];            // 4 MB
__device__ float d_bufB[NPIX];            // 4 MB

// ---------------------------------------------------------------------------
// Init: d0 = sparse > 0 ? sparse : blur   (pure elementwise)
// ---------------------------------------------------------------------------
__global__ __launch_bounds__(256) void init_kernel(
    const float* __restrict__ blur,
    const float* __restrict__ sparse)
{
    const int i = blockIdx.x * 256 + threadIdx.x;   // float4 index
    const float4 s = reinterpret_cast<const float4*>(sparse)[i];
    float4 v       = reinterpret_cast<const float4*>(blur)[i];
    v.x = (s.x > 0.f) ? s.x : v.x;
    v.y = (s.y > 0.f) ? s.y : v.y;
    v.z = (s.z > 0.f) ? s.z : v.z;
    v.w = (s.w > 0.f) ? s.w : v.w;
    reinterpret_cast<float4*>(d_bufA)[i] = v;
}

// ---------------------------------------------------------------------------
// One CSPN step:
//   d_new(p) = max_c [ sum_{3x3} g_c(n) d(n) / sum_{3x3} g_c(n) ],  g = |guid|
//   then sparse re-injection.
// 8 warps/CTA = 8 gate channels over an 8x128 tile. No shuffles: horizontal
// halos are scalar L1 loads with clamped addresses + fp masks. All loads per
// row are independent -> deep MLP; single barrier before the 8-way reduce.
// ---------------------------------------------------------------------------
__global__ __launch_bounds__(256, 3) void iter_kernel(
    int src_sel,                    // 0: read d_bufA, 1: read d_bufB
    float* __restrict__ dst_ext,    // if non-null, write here (final iter)
    const float* __restrict__ guid,
    const float* __restrict__ sparse)
{
    __shared__ float souts[CC][BANDH][TX]; // per-channel results, 32 KB

    const int tid  = threadIdx.x;
    const int lane = tid & 31;
    const int c    = tid >> 5;             // warp == channel
    const int bid  = blockIdx.x;
    const int xc   = bid & 3;
    const int yb   = (bid >> 2) & 31;
    const int b    = bid >> 7;
    const int x0   = xc * TX;
    const int y0   = yb * BANDH;

    const float* dsrc = src_sel ? d_bufB : d_bufA;
    float*       ddst = dst_ext ? dst_ext : (src_sel ? d_bufA : d_bufB);
    const float* dsb  = dsrc   + (size_t)b * PLANE;
    const float* spb  = sparse + (size_t)b * PLANE;
    float*       ddb  = ddst   + (size_t)b * PLANE;

    // ---- prefetch sparse for the epilogue (independent of everything) ----
    const int ep_row = tid >> 5;           // 0..7
    const int ep_c4  = tid & 31;
    const float4 sp_pre = *reinterpret_cast<const float4*>(
                              spb + (size_t)(y0 + ep_row) * WW + x0 + ep_c4 * 4);

    // ---- this warp's channel: stream 10 rows, rolling vertical sums ----
    const float* gc = guid + ((size_t)(b * CC + c)) * PLANE;
    const int   lx    = x0 + lane * 4;
    const int   lxm   = (lx > 0) ? (lx - 1) : 0;          // clamped halo cols
    const int   lxp   = (lx + 4 < WW) ? (lx + 4) : (WW - 1);
    const float lmask = (lx > 0) ? 1.f : 0.f;
    const float rmask = (lx + 4 < WW) ? 1.f : 0.f;

    float4 usp = make_float4(0.f,0.f,0.f,0.f), usc = usp;  // u = g*d rowsums
    float4 gsp = make_float4(0.f,0.f,0.f,0.f), gsc = gsp;  // g rowsums

    #pragma unroll
    for (int i = 0; i < NROWS; i++) {
        const int   ry    = y0 - 1 + i;
        const int   ryc   = (ry < 0) ? 0 : ((ry >= HH) ? (HH - 1) : ry);
        const float vmask = (ry >= 0 && ry < HH) ? 1.f : 0.f;
        const size_t ro   = (size_t)ryc * WW;

        // 6 independent loads (no predication, no shuffles)
        const float4 gr  = *reinterpret_cast<const float4*>(gc  + ro + lx);
        const float4 dr  = *reinterpret_cast<const float4*>(dsb + ro + lx);
        const float  g_l = gc [ro + lxm];
        const float  g_r = gc [ro + lxp];
        const float  d_l = dsb[ro + lxm];
        const float  d_r = dsb[ro + lxp];

        float4 ga;
        ga.x = fabsf(gr.x) * vmask; ga.y = fabsf(gr.y) * vmask;
        ga.z = fabsf(gr.z) * vmask; ga.w = fabsf(gr.w) * vmask;
        const float gm1 = fabsf(g_l) * (vmask * lmask);
        const float gp4 = fabsf(g_r) * (vmask * rmask);

        const float um1 = gm1  * d_l;
        const float u0  = ga.x * dr.x;
        const float u1  = ga.y * dr.y;
        const float u2  = ga.z * dr.z;
        const float u3  = ga.w * dr.w;
        const float up4 = gp4  * d_r;

        float4 usn, gsn;
        {
            const float t01 = u0 + u1, t12 = u1 + u2, t23 = u2 + u3;
            usn.x = um1 + t01; usn.y = t01 + u2;
            usn.z = t12 + u3;  usn.w = t23 + up4;
            const float s01 = ga.x + ga.y, s12 = ga.y + ga.z, s23 = ga.z + ga.w;
            gsn.x = gm1 + s01;  gsn.y = s01 + ga.z;
            gsn.z = s12 + ga.w; gsn.w = s23 + gp4;
        }

        if (i >= 2) {
            float4 o;
            o.x = __fdividef(usp.x + usc.x + usn.x, gsp.x + gsc.x + gsn.x);
            o.y = __fdividef(usp.y + usc.y + usn.y, gsp.y + gsc.y + gsn.y);
            o.z = __fdividef(usp.z + usc.z + usn.z, gsp.z + gsc.z + gsn.z);
            o.w = __fdividef(usp.w + usc.w + usn.w, gsp.w + gsc.w + gsn.w);
            *reinterpret_cast<float4*>(&souts[c][i - 2][lane * 4]) = o;
        }
        usp = usc; usc = usn;
        gsp = gsc; gsc = gsn;
    }
    __syncthreads();

    // ---- 8-way max reduce + sparse re-injection + float4 store ----
    {
        float4 m = *reinterpret_cast<const float4*>(&souts[0][ep_row][ep_c4 * 4]);
        #pragma unroll
        for (int cc = 1; cc < CC; cc++) {
            const float4 v = *reinterpret_cast<const float4*>(&souts[cc][ep_row][ep_c4 * 4]);
            m.x = fmaxf(m.x, v.x); m.y = fmaxf(m.y, v.y);
            m.z = fmaxf(m.z, v.z); m.w = fmaxf(m.w, v.w);
        }
        m.x = (sp_pre.x > 0.f) ? sp_pre.x : m.x;
        m.y = (sp_pre.y > 0.f) ? sp_pre.y : m.y;
        m.z = (sp_pre.z > 0.f) ? sp_pre.z : m.z;
        m.w = (sp_pre.w > 0.f) ? sp_pre.w : m.w;
        *reinterpret_cast<float4*>(ddb + (size_t)(y0 + ep_row) * WW + x0 + ep_c4 * 4) = m;
    }
}

extern "C" void kernel_launch(void* const* d_in, const int* in_sizes, int n_in,
                              void* d_out, int out_size)
{
    const float* guid   = (const float*)d_in[0];
    const float* blur   = (const float*)d_in[1];
    const float* sparse = (const float*)d_in[2];
    float*       out    = (float*)d_out;

    init_kernel<<<NPIX / 4 / 256, 256>>>(blur, sparse);

    // d0 lives in d_bufA. Even i reads A writes B, odd i reads B writes A.
    for (int i = 0; i < NITER; i++) {
        float* dst_ext = (i == NITER - 1) ? out : nullptr;
        iter_kernel<<<GRID_I, 256>>>(i & 1, dst_ext, guid, sparse);
    }
}